// round 12
// baseline (speedup 1.0000x reference)
#include <cuda_runtime.h>
#include <cstdint>

#define B        4
#define T        1024
#define HALF     256      // VALUE_DIM / 2
#define C        256
#define NLAB     64
#define VDIM     512

#define CBLK     128      // contract grid: (l=64) x (ch=2), 128 d's per block
#define CTHR     512      // 8 d-groups x 64 column-groups

// Scratch A[b][l][d] (65536 floats). Invariant: zero at entry to every launch
// (static zero-init; contract kernel consume-and-clears its exclusive slice).
__device__ float g_A[B * NLAB * HALF];

__device__ __forceinline__ void fma4(float4& acc, float a, const float4& w) {
    acc.x += a * w.x; acc.y += a * w.y; acc.z += a * w.z; acc.w += a * w.w;
}

// ---------------------------------------------------------------------------
// Kernel 1: scatter-accumulate (+ zero `out` in blocks 0..3)
//   A[b, label[b,t], d] += score[b,t] * weight[idx[b,t], off + d]
// One warp per token; two float4 loads + two float4 vector atomics per lane.
// ---------------------------------------------------------------------------
__global__ void __launch_bounds__(256)
vb_scatter_kernel(const int*   __restrict__ indices,
                  const float* __restrict__ scores,
                  const int*   __restrict__ label,
                  const int*   __restrict__ index_p,
                  const float* __restrict__ weight,
                  float*       __restrict__ out) {
    // Zero the (poisoned) output; contract runs in a later kernel -> ordered.
    if (blockIdx.x < B) out[blockIdx.x * C + threadIdx.x] = 0.0f;

    const int gwarp = (blockIdx.x * blockDim.x + threadIdx.x) >> 5;  // token
    const int lane  = threadIdx.x & 31;

    const int   idx = indices[gwarp];     // warp-uniform broadcast
    const float sc  = scores[gwarp];
    const int   lab = label[gwarp];
    const int   off = (*index_p == 1) ? HALF : 0;
    const int   b   = gwarp >> 10;        // gwarp = b*T + t

    const float4* wrow = reinterpret_cast<const float4*>(
        weight + (size_t)idx * VDIM + off);
    float4 v0 = __ldg(wrow + lane);
    float4 v1 = __ldg(wrow + lane + 32);
    v0.x *= sc; v0.y *= sc; v0.z *= sc; v0.w *= sc;
    v1.x *= sc; v1.y *= sc; v1.z *= sc; v1.w *= sc;

    float4* dst = reinterpret_cast<float4*>(
        g_A + (size_t)(b * NLAB + lab) * HALF);
    atomicAdd(dst + lane,      v0);
    atomicAdd(dst + lane + 32, v1);
}

// ---------------------------------------------------------------------------
// Kernel 2: contraction — ONE resident wave (128 blocks x 512 threads)
//   out[b, c] += sum_{d in 128-chunk} A[b,l,d] * W[l, off+d, c]
// Block (l, ch): l = bid>>1, ch = bid&1 (128 d's).
// Thread: c4 = tid&63 (4 output columns), dgrp = tid>>6 (0..7, 16 d's each).
// Per-thread work identical to the 2-wave version: 16 LDG.128 + 256 FMA4.
// ---------------------------------------------------------------------------
__global__ void __launch_bounds__(CTHR)
vb_contract_kernel(const float* __restrict__ W,
                   const int*   __restrict__ index_p,
                   float*       __restrict__ out) {
    __shared__ float  sA[B][128];
    __shared__ float4 s_part[7][64][B];   // partials from dgrp 1..7 (~28.7 KB)

    const int tid  = threadIdx.x;
    const int l    = blockIdx.x >> 1;
    const int ch   = blockIdx.x & 1;
    const int c4   = tid & 63;            // float4 column group
    const int dgrp = tid >> 6;            // 0..7, 16 d's each
    const int off  = (*index_p == 1) ? HALF : 0;

    // Issue the A-load first (its L2 latency hides under the W stream).
    const int ab  = tid >> 7;             // 0..3
    const int add = tid & 127;            // 0..127
    float* ap = &g_A[(size_t)(ab * NLAB + l) * HALF + ch * 128 + add];
    const float aval = __ldcg(ap);

    // W[l, off + ch*128 + dgrp*16 + i, c4*4 .. +3], i = 0..15
    const float4* Wp = reinterpret_cast<const float4*>(
        W + ((size_t)l * VDIM + off + ch * 128 + dgrp * 16) * C) + c4;

    float4 w[16];
#pragma unroll
    for (int i = 0; i < 16; i++)               // 16 LDG.128 in flight
        w[i] = __ldg(Wp + (size_t)i * (C / 4));

    // Publish A slice and clear it (exclusive ownership -> race-free).
    sA[ab][add] = aval;
    *ap = 0.0f;                                // restore zero invariant
    __syncthreads();

    float4 acc0 = {0,0,0,0}, acc1 = {0,0,0,0}, acc2 = {0,0,0,0}, acc3 = {0,0,0,0};
#pragma unroll
    for (int i = 0; i < 16; i++) {
        const int d = dgrp * 16 + i;           // local d within the 128-chunk
        fma4(acc0, sA[0][d], w[i]);
        fma4(acc1, sA[1][d], w[i]);
        fma4(acc2, sA[2][d], w[i]);
        fma4(acc3, sA[3][d], w[i]);
    }

    // Reduce the 8 d-groups: dgrp 1..7 park partials in smem, dgrp 0 sums.
    if (dgrp > 0) {
        s_part[dgrp - 1][c4][0] = acc0;
        s_part[dgrp - 1][c4][1] = acc1;
        s_part[dgrp - 1][c4][2] = acc2;
        s_part[dgrp - 1][c4][3] = acc3;
    }
    __syncthreads();

    if (dgrp == 0) {
#pragma unroll
        for (int k = 0; k < 7; k++) {
            const float4 p0 = s_part[k][c4][0];
            const float4 p1 = s_part[k][c4][1];
            const float4 p2 = s_part[k][c4][2];
            const float4 p3 = s_part[k][c4][3];
            acc0.x += p0.x; acc0.y += p0.y; acc0.z += p0.z; acc0.w += p0.w;
            acc1.x += p1.x; acc1.y += p1.y; acc1.z += p1.z; acc1.w += p1.w;
            acc2.x += p2.x; acc2.y += p2.y; acc2.z += p2.z; acc2.w += p2.w;
            acc3.x += p3.x; acc3.y += p3.y; acc3.z += p3.z; acc3.w += p3.w;
        }
        float4* o = reinterpret_cast<float4*>(out) + c4;
        atomicAdd(o,                acc0);
        atomicAdd(o + 1 * (C / 4),  acc1);
        atomicAdd(o + 2 * (C / 4),  acc2);
        atomicAdd(o + 3 * (C / 4),  acc3);
    }
}

// ---------------------------------------------------------------------------
// Inputs (metadata order):
//   0: indices (B,T) int32     1: scores (B,T) f32
//   2: W (64,512,256) f32      3: label (B,T) int32
//   4: index scalar int32      5: weight (262144,512) f32
// Output: (B, C) f32 = 1024 floats
// ---------------------------------------------------------------------------
extern "C" void kernel_launch(void* const* d_in, const int* in_sizes, int n_in,
                              void* d_out, int out_size) {
    const int*   indices = (const int*)  d_in[0];
    const float* scores  = (const float*)d_in[1];
    const float* W       = (const float*)d_in[2];
    const int*   label   = (const int*)  d_in[3];
    const int*   index_p = (const int*)  d_in[4];
    const float* weight  = (const float*)d_in[5];
    float*       out     = (float*)d_out;

    // 1) scatter (+ zero out): B*T = 4096 warps -> 512 blocks x 256 threads
    vb_scatter_kernel<<<512, 256>>>(indices, scores, label, index_p, weight, out);

    // 2) contraction: 64 labels x 2 d-chunks = 128 blocks, one resident wave
    vb_contract_kernel<<<CBLK, CTHR>>>(W, index_p, out);
}